// round 16
// baseline (speedup 1.0000x reference)
#include <cuda_runtime.h>
#include <cuda_bf16.h>
#include <stdint.h>
#include <math.h>

#define NB   64
#define NQ   900
#define NT   128
#define NCLS 91
#define CTS  928    // transposed column stride (float4-aligned: 928*4 % 16 == 0)
#define GT   1024   // greedy kernel threads (32 warps)

typedef unsigned long long u64;
typedef unsigned int       u32;

// Transposed cost copy: g_Ct[b][col][q] (column-contiguous)
__device__ float g_Ct[(size_t)NB * NT * CTS];

__device__ __forceinline__ u32 f2ord(float f) {
    u32 u = __float_as_uint(f);
    return (u & 0x80000000u) ? ~u : (u | 0x80000000u);
}
__device__ __forceinline__ u64 umin64(u64 a, u64 b) { return a < b ? a : b; }
__device__ __forceinline__ u32 redux_min(u32 v) {
    u32 r;
    asm("redux.sync.min.u32 %0, %1, 0xffffffff;" : "=r"(r) : "r"(v));
    return r;
}
// exact warp-wide u64 min (keys unique)
__device__ __forceinline__ u64 wredmin(u64 k) {
    u32 hi = (u32)(k >> 32);
    u32 mh = redux_min(hi);
    u32 lo = (hi == mh) ? (u32)k : 0xFFFFFFFFu;
    u32 ml = redux_min(lo);
    return ((u64)mh << 32) | ml;
}
__device__ __forceinline__ u64 mkkey(float v, int q, int c) {
    return ((u64)f2ord(v) << 18) | ((u32)q << 8) | (u32)c;
}

// exp(x) for x <= 0 without MUFU: 2^(x*log2e), deg-6 Taylor of 2^f, |f|<=0.5.
// rel err ~1.7e-7.  Runs entirely on FMA/ALU pipes.
__device__ __forceinline__ float exp_fma(float x) {
    const float L2E = 1.4426950408889634f;
    float t  = x * L2E;
    int   ki = __float2int_rn(t);
    float f  = t - (float)ki;
    float p  = 1.5403530393381608e-4f;
    p = fmaf(p, f, 1.3333558146428443e-3f);
    p = fmaf(p, f, 9.6181291076284770e-3f);
    p = fmaf(p, f, 5.5504108664821580e-2f);
    p = fmaf(p, f, 2.4022650695910070e-1f);
    p = fmaf(p, f, 6.9314718055994530e-1f);
    p = fmaf(p, f, 1.0f);
    return p * __int_as_float((ki + 127) << 23);
}

// ---------------------------------------------------------------------------
// Kernel 1: cost matrix (row-major) + transposed copy to g_Ct.
// ---------------------------------------------------------------------------
__global__ void __launch_bounds__(256) cost_kernel(
    const float* __restrict__ logits,
    const float* __restrict__ pboxes,
    const int*   __restrict__ labels,
    const float* __restrict__ tboxes,
    float* __restrict__ Cout)
{
    const int b    = blockIdx.y;
    const int tid  = threadIdx.x;
    const int lane = tid & 31;
    const int wid  = tid >> 5;
    const int q0   = blockIdx.x * 16;

    __shared__ float4 s_tb[NT];
    __shared__ float4 s_tx[NT];
    __shared__ float  s_ta[NT];
    __shared__ int    s_lab[NT];
    __shared__ float  s_exp[8][92];
    __shared__ float  s_t[16][132];

    if (tid < NT) {
        const float* tb = tboxes + ((size_t)b * NT + tid) * 4;
        float cx = tb[0], cy = tb[1], w = tb[2], h = tb[3];
        s_tb[tid] = make_float4(cx, cy, w, h);
        float x0 = cx - 0.5f * w, y0 = cy - 0.5f * h;
        float x1 = cx + 0.5f * w, y1 = cy + 0.5f * h;
        s_tx[tid] = make_float4(x0, y0, x1, y1);
        s_ta[tid] = (x1 - x0) * (y1 - y0);
        s_lab[tid] = labels[b * NT + tid];
    }
    __syncthreads();

    #pragma unroll
    for (int rr = 0; rr < 2; rr++) {
        const int qi = rr * 8 + wid;
        const int q  = q0 + qi;
        if (q >= NQ) continue;

        const float* lr = logits + ((size_t)b * NQ + q) * NCLS;
        float l0 = lr[lane];
        float l1 = lr[lane + 32];
        float l2 = (lane + 64 < NCLS) ? lr[lane + 64] : -INFINITY;
        float m = fmaxf(fmaxf(l0, l1), l2);
        #pragma unroll
        for (int o = 16; o; o >>= 1) m = fmaxf(m, __shfl_xor_sync(0xffffffffu, m, o));
        float e0 = exp_fma(l0 - m), e1 = exp_fma(l1 - m);
        float e2 = (lane + 64 < NCLS) ? exp_fma(l2 - m) : 0.0f;
        float ssum = e0 + e1 + e2;
        #pragma unroll
        for (int o = 16; o; o >>= 1) ssum += __shfl_xor_sync(0xffffffffu, ssum, o);
        s_exp[wid][lane] = e0;
        s_exp[wid][lane + 32] = e1;
        if (lane + 64 < NCLS) s_exp[wid][lane + 64] = e2;
        __syncwarp();
        float inv = 1.0f / ssum;

        const float* pbp = pboxes + ((size_t)b * NQ + q) * 4;
        float pcx = pbp[0], pcy = pbp[1], pw = pbp[2], ph = pbp[3];
        float px0 = pcx - 0.5f * pw, py0 = pcy - 0.5f * ph;
        float px1 = pcx + 0.5f * pw, py1 = pcy + 0.5f * ph;
        float pa  = (px1 - px0) * (py1 - py0);

        float cst[4];
        #pragma unroll
        for (int r = 0; r < 4; r++) {
            int t = (lane << 2) | r;
            float4 tb = s_tb[t];
            float4 tx = s_tx[t];
            float pl  = s_exp[wid][s_lab[t]] * inv;
            float l1c = fabsf(pcx - tb.x) + fabsf(pcy - tb.y)
                      + fabsf(pw - tb.z) + fabsf(ph - tb.w);
            float ix0 = fmaxf(px0, tx.x), iy0 = fmaxf(py0, tx.y);
            float ix1 = fminf(px1, tx.z), iy1 = fminf(py1, tx.w);
            float inter = fmaxf(ix1 - ix0, 0.0f) * fmaxf(iy1 - iy0, 0.0f);
            float uni   = pa + s_ta[t] - inter;
            float iou   = inter / uni;
            float cx0 = fminf(px0, tx.x), cy0 = fminf(py0, tx.y);
            float cx1 = fmaxf(px1, tx.z), cy1 = fmaxf(py1, tx.w);
            float ac  = fmaxf(cx1 - cx0, 0.0f) * fmaxf(cy1 - cy0, 0.0f);
            float giou = iou - (ac - uni) / ac;
            cst[r] = -pl + 5.0f * l1c - 2.0f * giou;
        }

        float* crow = Cout + ((size_t)b * NQ + q) * NT;
        *(float4*)(crow + (lane << 2)) = make_float4(cst[0], cst[1], cst[2], cst[3]);
        *(float4*)(&s_t[qi][lane << 2]) = make_float4(cst[0], cst[1], cst[2], cst[3]);
    }
    __syncthreads();

    // transposed write: thread -> (col = tid>>1, half = tid&1)
    {
        const int colg = tid >> 1;
        const int half = tid & 1;
        float v[8];
        #pragma unroll
        for (int k = 0; k < 8; k++) v[k] = s_t[half * 8 + k][colg];
        float* dst = g_Ct + ((size_t)b * NT + colg) * CTS + q0 + half * 8;
        *(float4*)(dst)     = make_float4(v[0], v[1], v[2], v[3]);
        *(float4*)(dst + 4) = make_float4(v[4], v[5], v[6], v[7]);
    }
}

// ---------------------------------------------------------------------------
// Kernel 2: greedy via sort-free multi-match rounds.  1024 threads per batch.
// Round: propose heads (atomicMin per row) -> Lmin = min loser key ->
// accept all winners with key < Lmin (== sorted prefix to first duplicate,
// exactly greedy) -> repair columns whose head row died.
// ---------------------------------------------------------------------------
__global__ void __launch_bounds__(GT) greedy_kernel(float* __restrict__ out)
{
    const int b    = blockIdx.x;
    const int tid  = threadIdx.x;
    const int lane = tid & 31;
    const int wid  = tid >> 5;
    const float* __restrict__ Ctb = g_Ct + (size_t)b * NT * CTS;

    __shared__ u64 colkey[NT];      // live column heads; ~0 = matched
    __shared__ u64 rowbest[NQ];     // per-row winner key (round-local)
    __shared__ u64 acclist[NT];
    __shared__ u64 s_lmin;
    __shared__ u32 rowdead[32];
    __shared__ int dlist[NT];
    __shared__ int s_cnt, s_dcnt, s_total;
    __shared__ int s_src[NT], s_tgt[NT];

    if (tid < NQ) rowbest[tid] = ~0ull;
    if (tid < 32) rowdead[tid] = 0u;
    if (tid == 0) s_total = 0;

    // ---- initial heads: warp w -> columns 4w..4w+3 (float4, coalesced) ----
    #pragma unroll
    for (int x = 0; x < 4; x++) {
        const int c = (wid << 2) + x;
        const float4* col4 = (const float4*)(Ctb + (size_t)c * CTS);
        u64 best = ~0ull;
        #pragma unroll
        for (int k = 0; k < 8; k++) {
            const int i4 = lane + k * 32;      // 225 float4 = 900 floats exactly
            if (i4 < 225) {
                float4 v = col4[i4];
                const int q = i4 * 4;
                best = umin64(best, mkkey(v.x, q + 0, c));
                best = umin64(best, mkkey(v.y, q + 1, c));
                best = umin64(best, mkkey(v.z, q + 2, c));
                best = umin64(best, mkkey(v.w, q + 3, c));
            }
        }
        best = wredmin(best);
        if (lane == 0) colkey[c] = best;
    }
    __syncthreads();

    for (;;) {
        // ---- phase 1: propose (row winners via atomicMin) ----
        if (tid < NT) {
            u64 k = colkey[tid];
            if (k != ~0ull) atomicMin(&rowbest[(int)((k >> 8) & 0x3FFu)], k);
        }
        if (tid == GT - 1) { s_lmin = ~0ull; s_cnt = 0; s_dcnt = 0; }
        __syncthreads();

        // ---- phase 2: Lmin = min over loser keys ----
        if (tid < NT) {
            u64 k = colkey[tid];
            if (k != ~0ull && rowbest[(int)((k >> 8) & 0x3FFu)] != k)
                atomicMin(&s_lmin, k);
        }
        __syncthreads();

        // ---- phase 3: accept winners with key < Lmin ----
        const int tbase = s_total;
        u64 myk = ~0ull;
        int myrow = -1;
        bool acc = false;
        if (tid < NT) {
            u64 k = colkey[tid];
            if (k != ~0ull) {
                const int q = (int)((k >> 8) & 0x3FFu);
                myk = k; myrow = q;
                if (rowbest[q] == k && k < s_lmin) {
                    acc = true;
                    int p = atomicAdd(&s_cnt, 1);
                    acclist[p] = k;
                    colkey[tid] = ~0ull;
                    atomicOr(&rowdead[q >> 5], 1u << (q & 31));
                }
            }
        }
        __syncthreads();

        // ---- phase 4: rank/store accepted; reset rowbest; dirty detect ----
        const int cnt = s_cnt;
        if (acc) {
            int rank = 0;
            for (int i = 0; i < cnt; i++) rank += (acclist[i] < myk);
            s_src[tbase + rank] = myrow;
            s_tgt[tbase + rank] = (int)(myk & 0xFFu);
        }
        if (myrow >= 0) rowbest[myrow] = ~0ull;   // all proposers reset their slot
        if (tid == GT - 1) s_total = tbase + cnt;
        if (tid < NT) {
            u64 k = colkey[tid];
            if (k != ~0ull) {
                const int q = (int)((k >> 8) & 0x3FFu);
                if ((rowdead[q >> 5] >> (q & 31)) & 1u) {
                    int p = atomicAdd(&s_dcnt, 1);
                    dlist[p] = tid;
                }
            }
        }
        __syncthreads();
        if (tbase + cnt >= NT) break;

        // ---- phase 5: repairs (one warp per dirty column, float4 loads) ----
        const int dcnt = s_dcnt;
        for (int idx = wid; idx < dcnt; idx += 32) {
            const int c = dlist[idx];
            const float4* col4 = (const float4*)(Ctb + (size_t)c * CTS);
            float4 v[8];
            #pragma unroll
            for (int k = 0; k < 8; k++) {
                const int i4 = lane + k * 32;
                v[k] = (i4 < 225) ? col4[i4] : make_float4(0.f, 0.f, 0.f, 0.f);
            }
            u64 best = ~0ull;
            #pragma unroll
            for (int k = 0; k < 8; k++) {
                const int i4 = lane + k * 32;
                if (i4 < 225) {
                    const int q = i4 * 4;
                    #pragma unroll
                    for (int e = 0; e < 4; e++) {
                        const int qq = q + e;
                        if (!((rowdead[qq >> 5] >> (qq & 31)) & 1u)) {
                            float vv = (e == 0) ? v[k].x : (e == 1) ? v[k].y
                                     : (e == 2) ? v[k].z : v[k].w;
                            best = umin64(best, mkkey(vv, qq, c));
                        }
                    }
                }
            }
            best = wredmin(best);
            if (lane == 0) colkey[c] = best;
        }
        __syncthreads();
    }

    if (tid < NT) {
        out[b * NT + tid]           = (float)s_src[tid];
        out[NB * NT + b * NT + tid] = (float)s_tgt[tid];
    }
}

// ---------------------------------------------------------------------------
extern "C" void kernel_launch(void* const* d_in, const int* in_sizes, int n_in,
                              void* d_out, int out_size) {
    const float* logits = (const float*)d_in[0];
    const float* pboxes = (const float*)d_in[1];
    const int*   labels = (const int*)d_in[2];
    const float* tboxes = (const float*)d_in[3];
    float* out = (float*)d_out;

    float* Cout = out + 2 * NB * NT;

    dim3 grid1((NQ + 15) / 16, NB);
    cost_kernel<<<grid1, 256>>>(logits, pboxes, labels, tboxes, Cout);
    greedy_kernel<<<NB, GT>>>(out);
}